// round 1
// baseline (speedup 1.0000x reference)
#include <cuda_runtime.h>
#include <math.h>

#define B_ 64
#define W_ 256
#define N_ 128
#define L_ 64
#define WCHUNK 128
#define PAD 65   // 65 mod 32 == 1 -> conflict-free column access

// Global scratch for per-(b,n) min distances (float bits, atomicMin-able since d >= 0)
__device__ unsigned int g_min[B_ * N_];

__global__ void init_kernel() {
    int i = blockIdx.x * blockDim.x + threadIdx.x;
    if (i < B_ * N_) g_min[i] = 0x7F800000u;  // +inf
}

// Each block: one (b, window-chunk of 128). Computes 128x128 dot tile (K=64),
// converts to squared distances, takes mins, merges into g_min.
__global__ void __launch_bounds__(256) dist_kernel(const float* __restrict__ x,
                                                   const float* __restrict__ sh) {
    extern __shared__ float smem[];
    float* sx  = smem;                      // [WCHUNK][PAD]
    float* ss  = smem + WCHUNK * PAD;       // [N_][PAD]
    float* sxx = ss + N_ * PAD;             // [WCHUNK] window norms
    float* ssn = sxx + WCHUNK;              // [N_]     shapelet norms
    unsigned int* umin = (unsigned int*)(ssn + N_);  // [N_] block-local min (bits)

    const int b     = blockIdx.x >> 1;
    const int wbase = (blockIdx.x & 1) * WCHUNK;
    const int tid   = threadIdx.x;

    const float* xb = x + ((size_t)b * W_ + wbase) * L_;

    // Load x chunk (128x64) and shapelets (128x64) into padded smem
    for (int i = tid; i < WCHUNK * L_; i += 256) {
        int r = i >> 6, c = i & 63;
        sx[r * PAD + c] = xb[i];
    }
    for (int i = tid; i < N_ * L_; i += 256) {
        int r = i >> 6, c = i & 63;
        ss[r * PAD + c] = sh[i];
    }
    if (tid < N_) umin[tid] = 0x7F800000u;
    __syncthreads();

    // Row norms: threads 0-127 -> window norms, 128-255 -> shapelet norms
    if (tid < WCHUNK) {
        float s = 0.f;
        #pragma unroll
        for (int k = 0; k < L_; k++) { float v = sx[tid * PAD + k]; s = fmaf(v, v, s); }
        sxx[tid] = s;
    } else {
        int n = tid - WCHUNK;
        float s = 0.f;
        #pragma unroll
        for (int k = 0; k < L_; k++) { float v = ss[n * PAD + k]; s = fmaf(v, v, s); }
        ssn[n] = s;
    }
    __syncthreads();

    // 8x8 register tile per thread; 16x16 thread grid
    const int tx = tid & 15;   // shapelet group
    const int ty = tid >> 4;   // window group
    float acc[8][8];
    #pragma unroll
    for (int i = 0; i < 8; i++)
        #pragma unroll
        for (int j = 0; j < 8; j++) acc[i][j] = 0.f;

    #pragma unroll 8
    for (int k = 0; k < L_; k++) {
        float a[8], c[8];
        #pragma unroll
        for (int i = 0; i < 8; i++) a[i] = sx[(ty + 16 * i) * PAD + k];
        #pragma unroll
        for (int j = 0; j < 8; j++) c[j] = ss[(tx + 16 * j) * PAD + k];
        #pragma unroll
        for (int i = 0; i < 8; i++)
            #pragma unroll
            for (int j = 0; j < 8; j++)
                acc[i][j] = fmaf(a[i], c[j], acc[i][j]);
    }

    // d^2 = ||x||^2 + ||s||^2 - 2*dot ; min over the 8 windows this thread owns,
    // sqrt once (monotone), then merge via shared atomicMin on float bits.
    float xxr[8];
    #pragma unroll
    for (int i = 0; i < 8; i++) xxr[i] = sxx[ty + 16 * i];

    #pragma unroll
    for (int j = 0; j < 8; j++) {
        float ssj = ssn[tx + 16 * j];
        float m = 3.402823466e+38f;
        #pragma unroll
        for (int i = 0; i < 8; i++) {
            float d2 = fmaf(-2.f, acc[i][j], xxr[i] + ssj);
            m = fminf(m, d2);
        }
        float d = sqrtf(fmaxf(m, 0.f));
        atomicMin(&umin[tx + 16 * j], __float_as_uint(d));
    }
    __syncthreads();

    if (tid < N_) atomicMin(&g_min[b * N_ + tid], umin[tid]);
}

// One block per batch element: logit = sum_n min_d[b][n]*w[n] + bias; sigmoid.
__global__ void cls_kernel(const float* __restrict__ w,
                           const float* __restrict__ bias,
                           float* __restrict__ out) {
    __shared__ float red[4];
    int b = blockIdx.x;
    int t = threadIdx.x;  // 128 threads
    float v = __uint_as_float(g_min[b * N_ + t]) * w[t];
    #pragma unroll
    for (int o = 16; o; o >>= 1) v += __shfl_xor_sync(0xffffffffu, v, o);
    if ((t & 31) == 0) red[t >> 5] = v;
    __syncthreads();
    if (t == 0) {
        float s = red[0] + red[1] + red[2] + red[3] + bias[0];
        out[b] = 1.f / (1.f + expf(-s));
    }
}

extern "C" void kernel_launch(void* const* d_in, const int* in_sizes, int n_in,
                              void* d_out, int out_size) {
    const float* x    = (const float*)d_in[0];
    const float* sh   = (const float*)d_in[1];
    const float* w    = (const float*)d_in[2];
    const float* bias = (const float*)d_in[3];
    float* out = (float*)d_out;

    const int smem_bytes = (WCHUNK + N_) * PAD * 4 + (WCHUNK + N_) * 4 + N_ * 4;
    cudaFuncSetAttribute(dist_kernel, cudaFuncAttributeMaxDynamicSharedMemorySize, smem_bytes);

    init_kernel<<<(B_ * N_ + 255) / 256, 256>>>();
    dist_kernel<<<B_ * (W_ / WCHUNK), 256, smem_bytes>>>(x, sh);
    cls_kernel<<<B_, N_>>>(w, bias, out);
}

// round 2
// speedup vs baseline: 1.1101x; 1.1101x over previous
#include <cuda_runtime.h>
#include <math.h>

#define B_ 64
#define W_ 256
#define N_ 128
#define L_ 64
#define WC 128      // windows per block (2 blocks per batch element)
#define PAD 130     // even (LDS.64 alignment), 130 mod 32 = 2 -> near-conflict-free

// Producer half-min d^2 per (b, n); written fresh every call (no init needed).
__device__ float g_part[B_ * N_];
// Per-batch producer-done flag. Zero at load; consumer resets after use.
__device__ int g_flag[B_];

#define FMA_F32X2(d, a, b, c) \
    asm("fma.rn.f32x2 %0, %1, %2, %3;" : "=l"(d) : "l"(a), "l"(b), "l"(c))

__global__ void __launch_bounds__(256) fused_kernel(const float* __restrict__ x,
                                                    const float* __restrict__ sh,
                                                    const float* __restrict__ w,
                                                    const float* __restrict__ bias,
                                                    float* __restrict__ out) {
    extern __shared__ float smem[];
    float* sx  = smem;                       // [L_][PAD]  windows, k-major
    float* ss  = sx + L_ * PAD;              // [L_][PAD]  shapelets, k-major
    float* sxx = ss + L_ * PAD;              // [WC]  window norms
    float* ssn = sxx + WC;                   // [N_]  shapelet norms
    unsigned int* umin = (unsigned int*)(ssn + N_);  // [N_] block-local min d^2 bits
    float* red = (float*)(umin + N_);        // [4] cls warp partials

    const int blk  = blockIdx.x;
    const int b    = blk >> 1;
    const int half = blk & 1;                // 0 = consumer, 1 = producer
    const int tid  = threadIdx.x;

    const float* xb = x + (size_t)(b * W_ + half * WC) * L_;

    // ---- load (transposed to k-major) ----
    for (int i = tid; i < WC * L_; i += 256) {
        int wdx = i >> 6, k = i & 63;
        sx[k * PAD + wdx] = xb[i];
    }
    for (int i = tid; i < N_ * L_; i += 256) {
        int n = i >> 6, k = i & 63;
        ss[k * PAD + n] = sh[i];
    }
    if (tid < N_) umin[tid] = 0x7F800000u;
    __syncthreads();

    // ---- norms ----
    if (tid < WC) {
        float s = 0.f;
        #pragma unroll
        for (int k = 0; k < L_; k++) { float v = sx[k * PAD + tid]; s = fmaf(v, v, s); }
        sxx[tid] = s;
    } else {
        int n = tid - WC;
        float s = 0.f;
        #pragma unroll
        for (int k = 0; k < L_; k++) { float v = ss[k * PAD + n]; s = fmaf(v, v, s); }
        ssn[n] = s;
    }
    __syncthreads();

    // ---- 128x128x64 dot tile, packed f32x2 FMA ----
    // thread owns windows 8*ty + [0,8) (as 4 packed pairs) x shapelets tx + 16*j
    const int tx = tid & 15;
    const int ty = tid >> 4;

    unsigned long long acc[4][8];
    #pragma unroll
    for (int m = 0; m < 4; m++)
        #pragma unroll
        for (int j = 0; j < 8; j++) acc[m][j] = 0ull;

    const float* sxr = sx + 8 * ty;   // window pair base within each k-row
    const float* ssr = ss + tx;       // shapelet base within each k-row

    #pragma unroll 8
    for (int k = 0; k < L_; k++) {
        unsigned long long a2[4];
        #pragma unroll
        for (int m = 0; m < 4; m++)
            a2[m] = *(const unsigned long long*)(sxr + k * PAD + 2 * m);
        unsigned long long c2[8];
        #pragma unroll
        for (int j = 0; j < 8; j++) {
            unsigned int cu = __float_as_uint(ssr[k * PAD + 16 * j]);
            c2[j] = ((unsigned long long)cu << 32) | cu;   // lane-dup
        }
        #pragma unroll
        for (int m = 0; m < 4; m++)
            #pragma unroll
            for (int j = 0; j < 8; j++)
                FMA_F32X2(acc[m][j], a2[m], c2[j], acc[m][j]);
    }

    // ---- d^2 = ||x||^2 + ||s||^2 - 2*dot; min over this thread's 8 windows ----
    float xx[8];
    #pragma unroll
    for (int i = 0; i < 8; i++) xx[i] = sxx[8 * ty + i];

    #pragma unroll
    for (int j = 0; j < 8; j++) {
        float sn = ssn[tx + 16 * j];
        float mn = 3.402823466e+38f;
        #pragma unroll
        for (int m = 0; m < 4; m++) {
            float dlo = __uint_as_float((unsigned int)acc[m][j]);
            float dhi = __uint_as_float((unsigned int)(acc[m][j] >> 32));
            mn = fminf(mn, fmaf(-2.f, dlo, xx[2 * m]     + sn));
            mn = fminf(mn, fmaf(-2.f, dhi, xx[2 * m + 1] + sn));
        }
        atomicMin(&umin[tx + 16 * j], __float_as_uint(fmaxf(mn, 0.f)));
    }
    __syncthreads();

    if (half == 1) {
        // ---- producer: publish half-min, raise flag ----
        if (tid < N_) g_part[b * N_ + tid] = __uint_as_float(umin[tid]);
        __syncthreads();
        if (tid == 0) { __threadfence(); atomicExch(&g_flag[b], 1); }
    } else {
        // ---- consumer: wait for sibling, merge, classify ----
        if (tid == 0) {
            while (atomicAdd(&g_flag[b], 0) == 0) { }
            __threadfence();
            g_flag[b] = 0;   // reset for next graph replay
        }
        __syncthreads();
        float v = 0.f;
        if (tid < N_) {
            float other = __ldcg(&g_part[b * N_ + tid]);   // bypass L1
            float d2 = fminf(__uint_as_float(umin[tid]), other);
            v = sqrtf(d2) * w[tid];
        }
        #pragma unroll
        for (int o = 16; o; o >>= 1) v += __shfl_xor_sync(0xffffffffu, v, o);
        if (tid < N_ && (tid & 31) == 0) red[tid >> 5] = v;
        __syncthreads();
        if (tid == 0) {
            float s = red[0] + red[1] + red[2] + red[3] + bias[0];
            out[b] = 1.f / (1.f + expf(-s));
        }
    }
}

extern "C" void kernel_launch(void* const* d_in, const int* in_sizes, int n_in,
                              void* d_out, int out_size) {
    const float* x    = (const float*)d_in[0];
    const float* sh   = (const float*)d_in[1];
    const float* w    = (const float*)d_in[2];
    const float* bias = (const float*)d_in[3];
    float* out = (float*)d_out;

    const int smem_bytes = (2 * L_ * PAD + WC + N_ + N_ + 4) * 4;
    cudaFuncSetAttribute(fused_kernel, cudaFuncAttributeMaxDynamicSharedMemorySize, smem_bytes);

    fused_kernel<<<2 * B_, 256, smem_bytes>>>(x, sh, w, bias, out);
}